// round 10
// baseline (speedup 1.0000x reference)
#include <cuda_runtime.h>
#include <cuda_bf16.h>
#include <cstdint>

#define N_NODES 150000
#define N_EDGES 2400000
#define D 128
#define ROWS_PER_BLK 64
#define DSTRIDE 136            // bf16 row stride: 272B -> 4-bank skew, conflict-free frags

#define SCAN_TILE 1024
#define SCAN_BLOCKS ((N_NODES + SCAN_TILE - 1) / SCAN_TILE)   // 147

// ------------------------- device scratch (no runtime alloc) -------------------------
__device__ int   g_cnt[N_NODES];
__device__ int   g_start[N_NODES];
__device__ int   g_cursor[N_NODES];
__device__ int   g_blocksums[SCAN_BLOCKS];
__device__ int2  g_edge_s[N_EDGES];               // CSR-ordered (col, val_bits)
// W^T split-bf16, padded [n][k] layout (n*DSTRIDE + k): [Wg_hi][Wg_lo][Wbi_hi][Wbi_lo]
__device__ __align__(16) __nv_bfloat16 g_W[4 * 128 * DSTRIDE];

// ------------------------- CSR build -------------------------
__global__ void zero_cnt_kernel() {
    int i = blockIdx.x * blockDim.x + threadIdx.x;
    if (i < N_NODES) g_cnt[i] = 0;
}

__global__ void hist_kernel(const int* __restrict__ erow) {
    int e = blockIdx.x * blockDim.x + threadIdx.x;
    if (e < N_EDGES) atomicAdd(&g_cnt[erow[e]], 1);
}

__global__ void scan1_kernel() {
    __shared__ int sh[256];
    int t = threadIdx.x;
    int base = blockIdx.x * SCAN_TILE + t * 4;
    int v[4];
#pragma unroll
    for (int j = 0; j < 4; j++)
        v[j] = (base + j < N_NODES) ? g_cnt[base + j] : 0;
    int s = v[0] + v[1] + v[2] + v[3];
    sh[t] = s;
    __syncthreads();
#pragma unroll
    for (int off = 1; off < 256; off <<= 1) {
        int x = (t >= off) ? sh[t - off] : 0;
        __syncthreads();
        sh[t] += x;
        __syncthreads();
    }
    int run = sh[t] - s;
#pragma unroll
    for (int j = 0; j < 4; j++) {
        if (base + j < N_NODES) g_start[base + j] = run;
        run += v[j];
    }
    if (t == 255) g_blocksums[blockIdx.x] = sh[255];
}

__global__ void scan2_kernel() {
    __shared__ int sh[256];
    int t = threadIdx.x;
    int v = (t < SCAN_BLOCKS) ? g_blocksums[t] : 0;
    sh[t] = v;
    __syncthreads();
#pragma unroll
    for (int off = 1; off < 256; off <<= 1) {
        int x = (t >= off) ? sh[t - off] : 0;
        __syncthreads();
        sh[t] += x;
        __syncthreads();
    }
    if (t < SCAN_BLOCKS) g_blocksums[t] = sh[t] - v;
}

__global__ void scan3_kernel() {
    int i = blockIdx.x * blockDim.x + threadIdx.x;
    if (i < N_NODES) {
        int s = g_start[i] + g_blocksums[i / SCAN_TILE];
        g_start[i] = s;
        g_cursor[i] = s;
    }
}

__global__ void fill_kernel(const int* __restrict__ erow,
                            const int* __restrict__ ecol,
                            const float* __restrict__ eval) {
    int e = blockIdx.x * blockDim.x + threadIdx.x;
    if (e < N_EDGES) {
        int r = erow[e];
        int pos = atomicAdd(&g_cursor[r], 1);
        g_edge_s[pos] = make_int2(ecol[e], __float_as_int(eval[e]));
    }
}

// ------------------------- W prep: transpose + split-bf16 -------------------------
__global__ void prep_w_kernel(const float* __restrict__ wgc, const float* __restrict__ wbi) {
    int i = blockIdx.x * blockDim.x + threadIdx.x;
    if (i >= 128 * 128) return;
    int k = i >> 7, n = i & 127;
    float vg = wgc[i];                     // wgc[k][n]
    float vb = wbi[i];
    __nv_bfloat16 gh = __float2bfloat16(vg);
    __nv_bfloat16 gl = __float2bfloat16(vg - __bfloat162float(gh));
    __nv_bfloat16 bh = __float2bfloat16(vb);
    __nv_bfloat16 bl = __float2bfloat16(vb - __bfloat162float(bh));
    int off = n * DSTRIDE + k;             // [n][k]
    g_W[off] = gh;
    g_W[128 * DSTRIDE + off] = gl;
    g_W[2 * 128 * DSTRIDE + off] = bh;
    g_W[3 * 128 * DSTRIDE + off] = bl;
}

// ------------------------- fused SpMM + dense mma + epilogue -------------------------
// smem layout (bf16 units):
#define A_SHI 0
#define A_SLO (64 * DSTRIDE)
#define A_BHI (2 * 64 * DSTRIDE)
#define A_BLO (3 * 64 * DSTRIDE)
#define W_OFF (4 * 64 * DSTRIDE)
#define SMEM_BF16 (W_OFF + 4 * 128 * DSTRIDE)
#define FBIAS_BYTE (SMEM_BF16 * 2)
#define SQ_BYTE (FBIAS_BYTE + 1024)
#define DENSE_SMEM (SQ_BYTE + 512)         // ~210 KB

__device__ __forceinline__ void mma_bf16(float* c, const uint32_t* a, const uint32_t* b) {
    asm volatile("mma.sync.aligned.m16n8k16.row.col.f32.bf16.bf16.f32 "
                 "{%0,%1,%2,%3}, {%4,%5,%6,%7}, {%8,%9}, {%0,%1,%2,%3};"
                 : "+f"(c[0]), "+f"(c[1]), "+f"(c[2]), "+f"(c[3])
                 : "r"(a[0]), "r"(a[1]), "r"(a[2]), "r"(a[3]), "r"(b[0]), "r"(b[1]));
}

__device__ __forceinline__ uint32_t pack_bf16x2(float a, float b) {
    __nv_bfloat162 t;
    t.x = __float2bfloat16(a);
    t.y = __float2bfloat16(b);
    return *reinterpret_cast<uint32_t*>(&t);
}

__global__ __launch_bounds__(256, 1)
void fused_kernel(const float* __restrict__ ego,
                  const float* __restrict__ bgc,
                  const float* __restrict__ bbi,
                  float* __restrict__ out) {
    extern __shared__ __nv_bfloat16 sm[];
    float* fbias = (float*)((char*)sm + FBIAS_BYTE);   // [0:128) bgc, [128:256) bbi
    float* sqbuf = (float*)((char*)sm + SQ_BYTE);      // [2][64]

    const int tid = threadIdx.x;
    const int w = tid >> 5, lane = tid & 31;
    const long row0 = (long)blockIdx.x * ROWS_PER_BLK;

    // copy prepped W (139,264 B) from L2 into smem
    {
        const float4* src = (const float4*)g_W;
        float4* dst = (float4*)(sm + W_OFF);
        for (int i = tid; i < (4 * 128 * DSTRIDE) / 8; i += 256) dst[i] = src[i];
    }
    if (tid < 128) fbias[tid] = bgc[tid];
    else fbias[tid] = bbi[tid - 128];

    // ---- phase 1: CSR gather (SpMM) directly into split-bf16 A tiles ----
    // warp w handles local rows [w*8, w*8+8); lane covers floats [4*lane, 4*lane+4)
    // coalesced per-warp fetch of 8 rows' (start, cnt): lane rr reads row w*8+rr
    int my_start = 0, my_cnt = 0;
    {
        long grl = row0 + w * 8 + lane;
        if (lane < 8 && grl < N_NODES) {
            my_start = g_start[grl];
            my_cnt = g_cnt[grl];
        }
    }
    const float4* ego4 = (const float4*)ego;
#pragma unroll 1
    for (int rr = 0; rr < 8; rr++) {
        const int r = w * 8 + rr;
        const long gr = row0 + r;
        float4 acc = make_float4(0.f, 0.f, 0.f, 0.f);
        float4 e4 = make_float4(0.f, 0.f, 0.f, 0.f);
        const int start = __shfl_sync(0xffffffffu, my_start, rr);
        const int cnt = __shfl_sync(0xffffffffu, my_cnt, rr);
        if (gr < N_NODES) {
            const int end = start + cnt;
            int i = start;
            for (; i + 1 < end; i += 2) {
                int2 ed0 = g_edge_s[i];
                int2 ed1 = g_edge_s[i + 1];
                float v0 = __int_as_float(ed0.y);
                float v1 = __int_as_float(ed1.y);
                float4 m0 = ego4[(size_t)ed0.x * 32 + lane];
                float4 m1 = ego4[(size_t)ed1.x * 32 + lane];
                acc.x = fmaf(v0, m0.x, acc.x); acc.y = fmaf(v0, m0.y, acc.y);
                acc.z = fmaf(v0, m0.z, acc.z); acc.w = fmaf(v0, m0.w, acc.w);
                acc.x = fmaf(v1, m1.x, acc.x); acc.y = fmaf(v1, m1.y, acc.y);
                acc.z = fmaf(v1, m1.z, acc.z); acc.w = fmaf(v1, m1.w, acc.w);
            }
            if (i < end) {
                int2 ed0 = g_edge_s[i];
                float v0 = __int_as_float(ed0.y);
                float4 m0 = ego4[(size_t)ed0.x * 32 + lane];
                acc.x = fmaf(v0, m0.x, acc.x); acc.y = fmaf(v0, m0.y, acc.y);
                acc.z = fmaf(v0, m0.z, acc.z); acc.w = fmaf(v0, m0.w, acc.w);
            }
            e4 = ego4[(size_t)gr * 32 + lane];
        }
        float4 b4 = make_float4(acc.x * e4.x, acc.y * e4.y, acc.z * e4.z, acc.w * e4.w);
        const int off = r * DSTRIDE + lane * 4;   // bf16 index, 8B aligned
        {
            uint32_t h0 = pack_bf16x2(acc.x, acc.y), h1 = pack_bf16x2(acc.z, acc.w);
            float r0 = acc.x - __bfloat162float(__float2bfloat16(acc.x));
            float r1 = acc.y - __bfloat162float(__float2bfloat16(acc.y));
            float r2 = acc.z - __bfloat162float(__float2bfloat16(acc.z));
            float r3 = acc.w - __bfloat162float(__float2bfloat16(acc.w));
            uint32_t l0 = pack_bf16x2(r0, r1), l1 = pack_bf16x2(r2, r3);
            *reinterpret_cast<uint2*>(sm + A_SHI + off) = make_uint2(h0, h1);
            *reinterpret_cast<uint2*>(sm + A_SLO + off) = make_uint2(l0, l1);
        }
        {
            uint32_t h0 = pack_bf16x2(b4.x, b4.y), h1 = pack_bf16x2(b4.z, b4.w);
            float r0 = b4.x - __bfloat162float(__float2bfloat16(b4.x));
            float r1 = b4.y - __bfloat162float(__float2bfloat16(b4.y));
            float r2 = b4.z - __bfloat162float(__float2bfloat16(b4.z));
            float r3 = b4.w - __bfloat162float(__float2bfloat16(b4.w));
            uint32_t l0 = pack_bf16x2(r0, r1), l1 = pack_bf16x2(r2, r3);
            *reinterpret_cast<uint2*>(sm + A_BHI + off) = make_uint2(h0, h1);
            *reinterpret_cast<uint2*>(sm + A_BLO + off) = make_uint2(l0, l1);
        }
    }
    __syncthreads();

    // ---- phase 2: dual GEMM on tensor cores ----
    const int mt = w >> 1;            // m-tile 0..3 (16 rows each)
    const int ch = w & 1;             // col half 0..1 (64 cols)
    const int g = lane >> 2, tig = lane & 3;
    const int arow = mt * 16 + g;

    float accG[8][4];
    float accB[8][4];
#pragma unroll
    for (int nt = 0; nt < 8; nt++)
#pragma unroll
        for (int j = 0; j < 4; j++) { accG[nt][j] = 0.f; accB[nt][j] = 0.f; }

    const __nv_bfloat16* wGh = sm + W_OFF;
    const __nv_bfloat16* wGl = wGh + 128 * DSTRIDE;
    const __nv_bfloat16* wBh = wGl + 128 * DSTRIDE;
    const __nv_bfloat16* wBl = wBh + 128 * DSTRIDE;

#pragma unroll 2
    for (int kc = 0; kc < 8; kc++) {
        const int k0 = kc * 16 + 2 * tig;
        uint32_t aSh[4], aSl[4], aBh[4], aBl[4];
        aSh[0] = *(const uint32_t*)(sm + A_SHI + arow * DSTRIDE + k0);
        aSh[1] = *(const uint32_t*)(sm + A_SHI + (arow + 8) * DSTRIDE + k0);
        aSh[2] = *(const uint32_t*)(sm + A_SHI + arow * DSTRIDE + k0 + 8);
        aSh[3] = *(const uint32_t*)(sm + A_SHI + (arow + 8) * DSTRIDE + k0 + 8);
        aSl[0] = *(const uint32_t*)(sm + A_SLO + arow * DSTRIDE + k0);
        aSl[1] = *(const uint32_t*)(sm + A_SLO + (arow + 8) * DSTRIDE + k0);
        aSl[2] = *(const uint32_t*)(sm + A_SLO + arow * DSTRIDE + k0 + 8);
        aSl[3] = *(const uint32_t*)(sm + A_SLO + (arow + 8) * DSTRIDE + k0 + 8);
        aBh[0] = *(const uint32_t*)(sm + A_BHI + arow * DSTRIDE + k0);
        aBh[1] = *(const uint32_t*)(sm + A_BHI + (arow + 8) * DSTRIDE + k0);
        aBh[2] = *(const uint32_t*)(sm + A_BHI + arow * DSTRIDE + k0 + 8);
        aBh[3] = *(const uint32_t*)(sm + A_BHI + (arow + 8) * DSTRIDE + k0 + 8);
        aBl[0] = *(const uint32_t*)(sm + A_BLO + arow * DSTRIDE + k0);
        aBl[1] = *(const uint32_t*)(sm + A_BLO + (arow + 8) * DSTRIDE + k0);
        aBl[2] = *(const uint32_t*)(sm + A_BLO + arow * DSTRIDE + k0 + 8);
        aBl[3] = *(const uint32_t*)(sm + A_BLO + (arow + 8) * DSTRIDE + k0 + 8);

#pragma unroll
        for (int nt = 0; nt < 8; nt++) {
            const int n = ch * 64 + nt * 8 + g;
            uint32_t bh[2], bl[2];
            bh[0] = *(const uint32_t*)(wGh + n * DSTRIDE + k0);
            bh[1] = *(const uint32_t*)(wGh + n * DSTRIDE + k0 + 8);
            bl[0] = *(const uint32_t*)(wGl + n * DSTRIDE + k0);
            bl[1] = *(const uint32_t*)(wGl + n * DSTRIDE + k0 + 8);
            mma_bf16(accG[nt], aSh, bh);
            mma_bf16(accG[nt], aSl, bh);
            mma_bf16(accG[nt], aSh, bl);
            bh[0] = *(const uint32_t*)(wBh + n * DSTRIDE + k0);
            bh[1] = *(const uint32_t*)(wBh + n * DSTRIDE + k0 + 8);
            bl[0] = *(const uint32_t*)(wBl + n * DSTRIDE + k0);
            bl[1] = *(const uint32_t*)(wBl + n * DSTRIDE + k0 + 8);
            mma_bf16(accB[nt], aBh, bh);
            mma_bf16(accB[nt], aBl, bh);
            mma_bf16(accB[nt], aBh, bl);
        }
    }

    // ---- epilogue: bias + leaky + sum, then row L2-normalize ----
    float sq_lo = 0.f, sq_hi = 0.f;
#pragma unroll
    for (int nt = 0; nt < 8; nt++) {
        const int col = ch * 64 + nt * 8 + 2 * tig;
        float bg0 = fbias[col], bg1 = fbias[col + 1];
        float bb0 = fbias[128 + col], bb1 = fbias[128 + col + 1];
        float x, y;
        x = accG[nt][0] + bg0; x = fmaxf(x, 0.2f * x);
        y = accB[nt][0] + bb0; y = fmaxf(y, 0.2f * y);
        accG[nt][0] = x + y; sq_lo = fmaf(accG[nt][0], accG[nt][0], sq_lo);
        x = accG[nt][1] + bg1; x = fmaxf(x, 0.2f * x);
        y = accB[nt][1] + bb1; y = fmaxf(y, 0.2f * y);
        accG[nt][1] = x + y; sq_lo = fmaf(accG[nt][1], accG[nt][1], sq_lo);
        x = accG[nt][2] + bg0; x = fmaxf(x, 0.2f * x);
        y = accB[nt][2] + bb0; y = fmaxf(y, 0.2f * y);
        accG[nt][2] = x + y; sq_hi = fmaf(accG[nt][2], accG[nt][2], sq_hi);
        x = accG[nt][3] + bg1; x = fmaxf(x, 0.2f * x);
        y = accB[nt][3] + bb1; y = fmaxf(y, 0.2f * y);
        accG[nt][3] = x + y; sq_hi = fmaf(accG[nt][3], accG[nt][3], sq_hi);
    }
#pragma unroll
    for (int m = 1; m <= 2; m <<= 1) {
        sq_lo += __shfl_xor_sync(0xffffffffu, sq_lo, m);
        sq_hi += __shfl_xor_sync(0xffffffffu, sq_hi, m);
    }
    if (tig == 0) {
        sqbuf[ch * 64 + mt * 16 + g] = sq_lo;
        sqbuf[ch * 64 + mt * 16 + g + 8] = sq_hi;
    }
    __syncthreads();
    float tot_lo = sqbuf[mt * 16 + g] + sqbuf[64 + mt * 16 + g];
    float tot_hi = sqbuf[mt * 16 + g + 8] + sqbuf[64 + mt * 16 + g + 8];
    float rn_lo = rsqrtf(fmaxf(tot_lo, 1e-12f));
    float rn_hi = rsqrtf(fmaxf(tot_hi, 1e-12f));

    const long grow_lo = row0 + mt * 16 + g;
    const long grow_hi = grow_lo + 8;
#pragma unroll
    for (int nt = 0; nt < 8; nt++) {
        const int col = ch * 64 + nt * 8 + 2 * tig;
        if (grow_lo < N_NODES) {
            float2 o = make_float2(accG[nt][0] * rn_lo, accG[nt][1] * rn_lo);
            *reinterpret_cast<float2*>(out + grow_lo * D + col) = o;
        }
        if (grow_hi < N_NODES) {
            float2 o = make_float2(accG[nt][2] * rn_hi, accG[nt][3] * rn_hi);
            *reinterpret_cast<float2*>(out + grow_hi * D + col) = o;
        }
    }
}

// ------------------------- launch -------------------------
extern "C" void kernel_launch(void* const* d_in, const int* in_sizes, int n_in,
                              void* d_out, int out_size) {
    const int*   erow = (const int*)d_in[0];
    const int*   ecol = (const int*)d_in[1];
    const float* eval = (const float*)d_in[2];
    const float* ego  = (const float*)d_in[3];
    const float* wgc  = (const float*)d_in[4];
    const float* bgc  = (const float*)d_in[5];
    const float* wbi  = (const float*)d_in[6];
    const float* bbi  = (const float*)d_in[7];
    float* out = (float*)d_out;

    // CSR build
    zero_cnt_kernel<<<(N_NODES + 255) / 256, 256>>>();
    hist_kernel<<<(N_EDGES + 255) / 256, 256>>>(erow);
    scan1_kernel<<<SCAN_BLOCKS, 256>>>();
    scan2_kernel<<<1, 256>>>();
    scan3_kernel<<<(N_NODES + 255) / 256, 256>>>();
    fill_kernel<<<(N_EDGES + 255) / 256, 256>>>(erow, ecol, eval);

    // W prep
    prep_w_kernel<<<64, 256>>>(wgc, wbi);

    // fused SpMM + dual GEMM + epilogue
    cudaFuncSetAttribute(fused_kernel, cudaFuncAttributeMaxDynamicSharedMemorySize, DENSE_SMEM);
    fused_kernel<<<(N_NODES + ROWS_PER_BLK - 1) / ROWS_PER_BLK, 256, DENSE_SMEM>>>(
        ego, bgc, bbi, out);
}

// round 11
// speedup vs baseline: 1.3394x; 1.3394x over previous
#include <cuda_runtime.h>
#include <cuda_bf16.h>
#include <cstdint>

#define N_NODES 150000
#define N_EDGES 2400000
#define D 128
#define ROWS_PER_BLK 64
#define DSTRIDE 136            // bf16 row stride: 272B -> 4-bank skew, conflict-free frags

#define SCAN_TILE 1024
#define SCAN_BLOCKS ((N_NODES + SCAN_TILE - 1) / SCAN_TILE)   // 147

// ------------------------- device scratch (no runtime alloc) -------------------------
__device__ float g_side[(size_t)N_NODES * D];     // 76.8 MB
__device__ int   g_cnt[N_NODES];
__device__ int   g_start[N_NODES];
__device__ int   g_cursor[N_NODES];
__device__ int   g_blocksums[SCAN_BLOCKS];
__device__ int2  g_edge_s[N_EDGES];               // CSR-ordered (col, val_bits)
// W^T split-bf16, padded [n][k] layout (n*DSTRIDE + k): [Wg_hi][Wg_lo][Wbi_hi][Wbi_lo]
__device__ __align__(16) __nv_bfloat16 g_W[4 * 128 * DSTRIDE];

// ------------------------- streaming access helpers -------------------------
__device__ __forceinline__ int2 ldcs_int2(const int2* p) {
    int2 v;
    asm volatile("ld.global.cs.v2.b32 {%0,%1}, [%2];" : "=r"(v.x), "=r"(v.y) : "l"(p));
    return v;
}
__device__ __forceinline__ void stcs_int2(int2* p, int2 v) {
    asm volatile("st.global.cs.v2.b32 [%0], {%1,%2};" :: "l"(p), "r"(v.x), "r"(v.y) : "memory");
}
__device__ __forceinline__ void stcs_float4(float4* p, float4 v) {
    asm volatile("st.global.cs.v4.f32 [%0], {%1,%2,%3,%4};"
                 :: "l"(p), "f"(v.x), "f"(v.y), "f"(v.z), "f"(v.w) : "memory");
}

// ------------------------- CSR build -------------------------
__global__ void zero_cnt_kernel() {
    int i = blockIdx.x * blockDim.x + threadIdx.x;
    if (i < N_NODES) g_cnt[i] = 0;
}

__global__ void hist_kernel(const int* __restrict__ erow) {
    int e = blockIdx.x * blockDim.x + threadIdx.x;
    if (e < N_EDGES) atomicAdd(&g_cnt[erow[e]], 1);
}

__global__ void scan1_kernel() {
    __shared__ int sh[256];
    int t = threadIdx.x;
    int base = blockIdx.x * SCAN_TILE + t * 4;
    int v[4];
#pragma unroll
    for (int j = 0; j < 4; j++)
        v[j] = (base + j < N_NODES) ? g_cnt[base + j] : 0;
    int s = v[0] + v[1] + v[2] + v[3];
    sh[t] = s;
    __syncthreads();
#pragma unroll
    for (int off = 1; off < 256; off <<= 1) {
        int x = (t >= off) ? sh[t - off] : 0;
        __syncthreads();
        sh[t] += x;
        __syncthreads();
    }
    int run = sh[t] - s;
#pragma unroll
    for (int j = 0; j < 4; j++) {
        if (base + j < N_NODES) g_start[base + j] = run;
        run += v[j];
    }
    if (t == 255) g_blocksums[blockIdx.x] = sh[255];
}

__global__ void scan2_kernel() {
    __shared__ int sh[256];
    int t = threadIdx.x;
    int v = (t < SCAN_BLOCKS) ? g_blocksums[t] : 0;
    sh[t] = v;
    __syncthreads();
#pragma unroll
    for (int off = 1; off < 256; off <<= 1) {
        int x = (t >= off) ? sh[t - off] : 0;
        __syncthreads();
        sh[t] += x;
        __syncthreads();
    }
    if (t < SCAN_BLOCKS) g_blocksums[t] = sh[t] - v;
}

__global__ void scan3_kernel() {
    int i = blockIdx.x * blockDim.x + threadIdx.x;
    if (i < N_NODES) {
        int s = g_start[i] + g_blocksums[i / SCAN_TILE];
        g_start[i] = s;
        g_cursor[i] = s;
    }
}

__global__ void fill_kernel(const int* __restrict__ erow,
                            const int* __restrict__ ecol,
                            const float* __restrict__ eval) {
    int e = blockIdx.x * blockDim.x + threadIdx.x;
    if (e < N_EDGES) {
        int r = erow[e];
        int pos = atomicAdd(&g_cursor[r], 1);
        stcs_int2(&g_edge_s[pos], make_int2(ecol[e], __float_as_int(eval[e])));
    }
}

// ------------------------- SpMM: warp per row, 4-wide unroll, streaming hints -------------------------
__global__ __launch_bounds__(256)
void spmm_csr_kernel(const float* __restrict__ ego) {
    int gw = (blockIdx.x * blockDim.x + threadIdx.x) >> 5;
    int lane = threadIdx.x & 31;
    if (gw >= N_NODES) return;
    int start = g_start[gw];
    int end = start + g_cnt[gw];
    const float4* ego4 = (const float4*)ego;
    float4 acc = make_float4(0.f, 0.f, 0.f, 0.f);
    int i = start;
    for (; i + 3 < end; i += 4) {
        int2 e0 = ldcs_int2(&g_edge_s[i]);
        int2 e1 = ldcs_int2(&g_edge_s[i + 1]);
        int2 e2 = ldcs_int2(&g_edge_s[i + 2]);
        int2 e3 = ldcs_int2(&g_edge_s[i + 3]);
        float4 m0 = ego4[(size_t)e0.x * 32 + lane];
        float4 m1 = ego4[(size_t)e1.x * 32 + lane];
        float4 m2 = ego4[(size_t)e2.x * 32 + lane];
        float4 m3 = ego4[(size_t)e3.x * 32 + lane];
        float v0 = __int_as_float(e0.y), v1 = __int_as_float(e1.y);
        float v2 = __int_as_float(e2.y), v3 = __int_as_float(e3.y);
        acc.x = fmaf(v0, m0.x, acc.x); acc.y = fmaf(v0, m0.y, acc.y);
        acc.z = fmaf(v0, m0.z, acc.z); acc.w = fmaf(v0, m0.w, acc.w);
        acc.x = fmaf(v1, m1.x, acc.x); acc.y = fmaf(v1, m1.y, acc.y);
        acc.z = fmaf(v1, m1.z, acc.z); acc.w = fmaf(v1, m1.w, acc.w);
        acc.x = fmaf(v2, m2.x, acc.x); acc.y = fmaf(v2, m2.y, acc.y);
        acc.z = fmaf(v2, m2.z, acc.z); acc.w = fmaf(v2, m2.w, acc.w);
        acc.x = fmaf(v3, m3.x, acc.x); acc.y = fmaf(v3, m3.y, acc.y);
        acc.z = fmaf(v3, m3.z, acc.z); acc.w = fmaf(v3, m3.w, acc.w);
    }
    for (; i < end; i++) {
        int2 e0 = ldcs_int2(&g_edge_s[i]);
        float v0 = __int_as_float(e0.y);
        float4 m0 = ego4[(size_t)e0.x * 32 + lane];
        acc.x = fmaf(v0, m0.x, acc.x); acc.y = fmaf(v0, m0.y, acc.y);
        acc.z = fmaf(v0, m0.z, acc.z); acc.w = fmaf(v0, m0.w, acc.w);
    }
    stcs_float4(&reinterpret_cast<float4*>(g_side)[(size_t)gw * 32 + lane], acc);
}

// ------------------------- W prep: transpose + split-bf16 -------------------------
__global__ void prep_w_kernel(const float* __restrict__ wgc, const float* __restrict__ wbi) {
    int i = blockIdx.x * blockDim.x + threadIdx.x;
    if (i >= 128 * 128) return;
    int k = i >> 7, n = i & 127;
    float vg = wgc[i];                     // wgc[k][n]
    float vb = wbi[i];
    __nv_bfloat16 gh = __float2bfloat16(vg);
    __nv_bfloat16 gl = __float2bfloat16(vg - __bfloat162float(gh));
    __nv_bfloat16 bh = __float2bfloat16(vb);
    __nv_bfloat16 bl = __float2bfloat16(vb - __bfloat162float(bh));
    int off = n * DSTRIDE + k;             // [n][k]
    g_W[off] = gh;
    g_W[128 * DSTRIDE + off] = gl;
    g_W[2 * 128 * DSTRIDE + off] = bh;
    g_W[3 * 128 * DSTRIDE + off] = bl;
}

// ------------------------- dense: mma.sync bf16-split -------------------------
#define A_SHI 0
#define A_SLO (64 * DSTRIDE)
#define A_BHI (2 * 64 * DSTRIDE)
#define A_BLO (3 * 64 * DSTRIDE)
#define W_OFF (4 * 64 * DSTRIDE)
#define SMEM_BF16 (W_OFF + 4 * 128 * DSTRIDE)
#define FBIAS_BYTE (SMEM_BF16 * 2)
#define SQ_BYTE (FBIAS_BYTE + 1024)
#define DENSE_SMEM (SQ_BYTE + 512)         // ~210 KB

__device__ __forceinline__ void mma_bf16(float* c, const uint32_t* a, const uint32_t* b) {
    asm volatile("mma.sync.aligned.m16n8k16.row.col.f32.bf16.bf16.f32 "
                 "{%0,%1,%2,%3}, {%4,%5,%6,%7}, {%8,%9}, {%0,%1,%2,%3};"
                 : "+f"(c[0]), "+f"(c[1]), "+f"(c[2]), "+f"(c[3])
                 : "r"(a[0]), "r"(a[1]), "r"(a[2]), "r"(a[3]), "r"(b[0]), "r"(b[1]));
}

__device__ __forceinline__ uint32_t pack_bf16x2(float a, float b) {
    __nv_bfloat162 t;
    t.x = __float2bfloat16(a);
    t.y = __float2bfloat16(b);
    return *reinterpret_cast<uint32_t*>(&t);
}

__global__ __launch_bounds__(256, 1)
void dense_mma_kernel(const float* __restrict__ ego,
                      const float* __restrict__ bgc,
                      const float* __restrict__ bbi,
                      float* __restrict__ out) {
    extern __shared__ __nv_bfloat16 sm[];
    float* fbias = (float*)((char*)sm + FBIAS_BYTE);   // [0:128) bgc, [128:256) bbi
    float* sqbuf = (float*)((char*)sm + SQ_BYTE);      // [2][64]

    const int tid = threadIdx.x;
    const long row0 = (long)blockIdx.x * ROWS_PER_BLK;

    // copy prepped W (139,264 B) from L2 into smem
    {
        const float4* src = (const float4*)g_W;
        float4* dst = (float4*)(sm + W_OFF);
        for (int i = tid; i < (4 * 128 * DSTRIDE) / 8; i += 256) dst[i] = src[i];
    }
    if (tid < 128) fbias[tid] = bgc[tid];
    else fbias[tid] = bbi[tid - 128];

    // stage A tiles: side hi/lo and (ego*side) hi/lo
    for (int i = tid; i < ROWS_PER_BLK * 32; i += 256) {
        int r = i >> 5, c4 = i & 31;
        long gr = row0 + r;
        float4 s4 = make_float4(0.f, 0.f, 0.f, 0.f);
        float4 b4 = s4;
        if (gr < N_NODES) {
            s4 = reinterpret_cast<const float4*>(g_side + gr * D)[c4];
            float4 e4 = reinterpret_cast<const float4*>(ego + gr * D)[c4];
            b4 = make_float4(s4.x * e4.x, s4.y * e4.y, s4.z * e4.z, s4.w * e4.w);
        }
        int off = r * DSTRIDE + c4 * 4;   // bf16 index, 8B aligned
        {
            uint32_t h0 = pack_bf16x2(s4.x, s4.y), h1 = pack_bf16x2(s4.z, s4.w);
            float r0 = s4.x - __bfloat162float(__float2bfloat16(s4.x));
            float r1 = s4.y - __bfloat162float(__float2bfloat16(s4.y));
            float r2 = s4.z - __bfloat162float(__float2bfloat16(s4.z));
            float r3 = s4.w - __bfloat162float(__float2bfloat16(s4.w));
            uint32_t l0 = pack_bf16x2(r0, r1), l1 = pack_bf16x2(r2, r3);
            *reinterpret_cast<uint2*>(sm + A_SHI + off) = make_uint2(h0, h1);
            *reinterpret_cast<uint2*>(sm + A_SLO + off) = make_uint2(l0, l1);
        }
        {
            uint32_t h0 = pack_bf16x2(b4.x, b4.y), h1 = pack_bf16x2(b4.z, b4.w);
            float r0 = b4.x - __bfloat162float(__float2bfloat16(b4.x));
            float r1 = b4.y - __bfloat162float(__float2bfloat16(b4.y));
            float r2 = b4.z - __bfloat162float(__float2bfloat16(b4.z));
            float r3 = b4.w - __bfloat162float(__float2bfloat16(b4.w));
            uint32_t l0 = pack_bf16x2(r0, r1), l1 = pack_bf16x2(r2, r3);
            *reinterpret_cast<uint2*>(sm + A_BHI + off) = make_uint2(h0, h1);
            *reinterpret_cast<uint2*>(sm + A_BLO + off) = make_uint2(l0, l1);
        }
    }
    __syncthreads();

    const int w = tid >> 5, lane = tid & 31;
    const int mt = w >> 1;            // m-tile 0..3 (16 rows each)
    const int ch = w & 1;             // col half 0..1 (64 cols)
    const int g = lane >> 2, tig = lane & 3;
    const int arow = mt * 16 + g;

    float accG[8][4];
    float accB[8][4];
#pragma unroll
    for (int nt = 0; nt < 8; nt++)
#pragma unroll
        for (int j = 0; j < 4; j++) { accG[nt][j] = 0.f; accB[nt][j] = 0.f; }

    const __nv_bfloat16* wGh = sm + W_OFF;
    const __nv_bfloat16* wGl = wGh + 128 * DSTRIDE;
    const __nv_bfloat16* wBh = wGl + 128 * DSTRIDE;
    const __nv_bfloat16* wBl = wBh + 128 * DSTRIDE;

#pragma unroll 2
    for (int kc = 0; kc < 8; kc++) {
        const int k0 = kc * 16 + 2 * tig;
        uint32_t aSh[4], aSl[4], aBh[4], aBl[4];
        aSh[0] = *(const uint32_t*)(sm + A_SHI + arow * DSTRIDE + k0);
        aSh[1] = *(const uint32_t*)(sm + A_SHI + (arow + 8) * DSTRIDE + k0);
        aSh[2] = *(const uint32_t*)(sm + A_SHI + arow * DSTRIDE + k0 + 8);
        aSh[3] = *(const uint32_t*)(sm + A_SHI + (arow + 8) * DSTRIDE + k0 + 8);
        aSl[0] = *(const uint32_t*)(sm + A_SLO + arow * DSTRIDE + k0);
        aSl[1] = *(const uint32_t*)(sm + A_SLO + (arow + 8) * DSTRIDE + k0);
        aSl[2] = *(const uint32_t*)(sm + A_SLO + arow * DSTRIDE + k0 + 8);
        aSl[3] = *(const uint32_t*)(sm + A_SLO + (arow + 8) * DSTRIDE + k0 + 8);
        aBh[0] = *(const uint32_t*)(sm + A_BHI + arow * DSTRIDE + k0);
        aBh[1] = *(const uint32_t*)(sm + A_BHI + (arow + 8) * DSTRIDE + k0);
        aBh[2] = *(const uint32_t*)(sm + A_BHI + arow * DSTRIDE + k0 + 8);
        aBh[3] = *(const uint32_t*)(sm + A_BHI + (arow + 8) * DSTRIDE + k0 + 8);
        aBl[0] = *(const uint32_t*)(sm + A_BLO + arow * DSTRIDE + k0);
        aBl[1] = *(const uint32_t*)(sm + A_BLO + (arow + 8) * DSTRIDE + k0);
        aBl[2] = *(const uint32_t*)(sm + A_BLO + arow * DSTRIDE + k0 + 8);
        aBl[3] = *(const uint32_t*)(sm + A_BLO + (arow + 8) * DSTRIDE + k0 + 8);

#pragma unroll
        for (int nt = 0; nt < 8; nt++) {
            const int n = ch * 64 + nt * 8 + g;
            uint32_t bh[2], bl[2];
            bh[0] = *(const uint32_t*)(wGh + n * DSTRIDE + k0);
            bh[1] = *(const uint32_t*)(wGh + n * DSTRIDE + k0 + 8);
            bl[0] = *(const uint32_t*)(wGl + n * DSTRIDE + k0);
            bl[1] = *(const uint32_t*)(wGl + n * DSTRIDE + k0 + 8);
            mma_bf16(accG[nt], aSh, bh);
            mma_bf16(accG[nt], aSl, bh);
            mma_bf16(accG[nt], aSh, bl);
            bh[0] = *(const uint32_t*)(wBh + n * DSTRIDE + k0);
            bh[1] = *(const uint32_t*)(wBh + n * DSTRIDE + k0 + 8);
            bl[0] = *(const uint32_t*)(wBl + n * DSTRIDE + k0);
            bl[1] = *(const uint32_t*)(wBl + n * DSTRIDE + k0 + 8);
            mma_bf16(accB[nt], aBh, bh);
            mma_bf16(accB[nt], aBl, bh);
            mma_bf16(accB[nt], aBh, bl);
        }
    }

    // epilogue: bias + leaky + sum, then row L2-normalize
    float sq_lo = 0.f, sq_hi = 0.f;
#pragma unroll
    for (int nt = 0; nt < 8; nt++) {
        const int col = ch * 64 + nt * 8 + 2 * tig;
        float bg0 = fbias[col], bg1 = fbias[col + 1];
        float bb0 = fbias[128 + col], bb1 = fbias[128 + col + 1];
        float x, y;
        x = accG[nt][0] + bg0; x = fmaxf(x, 0.2f * x);
        y = accB[nt][0] + bb0; y = fmaxf(y, 0.2f * y);
        accG[nt][0] = x + y; sq_lo = fmaf(accG[nt][0], accG[nt][0], sq_lo);
        x = accG[nt][1] + bg1; x = fmaxf(x, 0.2f * x);
        y = accB[nt][1] + bb1; y = fmaxf(y, 0.2f * y);
        accG[nt][1] = x + y; sq_lo = fmaf(accG[nt][1], accG[nt][1], sq_lo);
        x = accG[nt][2] + bg0; x = fmaxf(x, 0.2f * x);
        y = accB[nt][2] + bb0; y = fmaxf(y, 0.2f * y);
        accG[nt][2] = x + y; sq_hi = fmaf(accG[nt][2], accG[nt][2], sq_hi);
        x = accG[nt][3] + bg1; x = fmaxf(x, 0.2f * x);
        y = accB[nt][3] + bb1; y = fmaxf(y, 0.2f * y);
        accG[nt][3] = x + y; sq_hi = fmaf(accG[nt][3], accG[nt][3], sq_hi);
    }
#pragma unroll
    for (int m = 1; m <= 2; m <<= 1) {
        sq_lo += __shfl_xor_sync(0xffffffffu, sq_lo, m);
        sq_hi += __shfl_xor_sync(0xffffffffu, sq_hi, m);
    }
    if (tig == 0) {
        sqbuf[ch * 64 + mt * 16 + g] = sq_lo;
        sqbuf[ch * 64 + mt * 16 + g + 8] = sq_hi;
    }
    __syncthreads();
    float tot_lo = sqbuf[mt * 16 + g] + sqbuf[64 + mt * 16 + g];
    float tot_hi = sqbuf[mt * 16 + g + 8] + sqbuf[64 + mt * 16 + g + 8];
    float rn_lo = rsqrtf(fmaxf(tot_lo, 1e-12f));
    float rn_hi = rsqrtf(fmaxf(tot_hi, 1e-12f));

    const long grow_lo = row0 + mt * 16 + g;
    const long grow_hi = grow_lo + 8;
#pragma unroll
    for (int nt = 0; nt < 8; nt++) {
        const int col = ch * 64 + nt * 8 + 2 * tig;
        if (grow_lo < N_NODES) {
            float2 o = make_float2(accG[nt][0] * rn_lo, accG[nt][1] * rn_lo);
            *reinterpret_cast<float2*>(out + grow_lo * D + col) = o;
        }
        if (grow_hi < N_NODES) {
            float2 o = make_float2(accG[nt][2] * rn_hi, accG[nt][3] * rn_hi);
            *reinterpret_cast<float2*>(out + grow_hi * D + col) = o;
        }
    }
}

// ------------------------- launch -------------------------
extern "C" void kernel_launch(void* const* d_in, const int* in_sizes, int n_in,
                              void* d_out, int out_size) {
    const int*   erow = (const int*)d_in[0];
    const int*   ecol = (const int*)d_in[1];
    const float* eval = (const float*)d_in[2];
    const float* ego  = (const float*)d_in[3];
    const float* wgc  = (const float*)d_in[4];
    const float* bgc  = (const float*)d_in[5];
    const float* wbi  = (const float*)d_in[6];
    const float* bbi  = (const float*)d_in[7];
    float* out = (float*)d_out;

    // CSR build
    zero_cnt_kernel<<<(N_NODES + 255) / 256, 256>>>();
    hist_kernel<<<(N_EDGES + 255) / 256, 256>>>(erow);
    scan1_kernel<<<SCAN_BLOCKS, 256>>>();
    scan2_kernel<<<1, 256>>>();
    scan3_kernel<<<(N_NODES + 255) / 256, 256>>>();
    fill_kernel<<<(N_EDGES + 255) / 256, 256>>>(erow, ecol, eval);

    // SpMM: warp per row
    long spmm_threads = (long)N_NODES * 32;
    spmm_csr_kernel<<<(int)((spmm_threads + 255) / 256), 256>>>(ego);

    // W prep + dense tensor-core transform
    prep_w_kernel<<<64, 256>>>(wgc, wbi);
    cudaFuncSetAttribute(dense_mma_kernel, cudaFuncAttributeMaxDynamicSharedMemorySize, DENSE_SMEM);
    dense_mma_kernel<<<(N_NODES + ROWS_PER_BLK - 1) / ROWS_PER_BLK, 256, DENSE_SMEM>>>(
        ego, bgc, bbi, out);
}

// round 15
// speedup vs baseline: 1.6084x; 1.2009x over previous
#include <cuda_runtime.h>
#include <cuda_bf16.h>
#include <cstdint>

#define N_NODES 150000
#define N_EDGES 2400000
#define D 128
#define ROWS_PER_BLK 64
#define N_TILES ((N_NODES + ROWS_PER_BLK - 1) / ROWS_PER_BLK)   // 2344
#define DENSE_GRID 148
#define DSTRIDE 136            // bf16 row stride: 272B -> 4-bank skew, conflict-free frags

#define SCAN_TILE 1024
#define SCAN_BLOCKS ((N_NODES + SCAN_TILE - 1) / SCAN_TILE)   // 147

// ------------------------- device scratch (no runtime alloc) -------------------------
__device__ float g_side[(size_t)N_NODES * D];     // 76.8 MB
__device__ int   g_cnt[N_NODES];
__device__ int   g_start[N_NODES];
__device__ int   g_cursor[N_NODES];
__device__ int   g_blocksums[SCAN_BLOCKS];
__device__ int2  g_edge_s[N_EDGES];               // CSR-ordered (col, val_bits)
// W^T split-bf16, padded [n][k] layout (n*DSTRIDE + k): [Wg_hi][Wg_lo][Wbi_hi][Wbi_lo]
__device__ __align__(16) __nv_bfloat16 g_W[4 * 128 * DSTRIDE];

// ------------------------- streaming access helpers -------------------------
__device__ __forceinline__ int2 ldcs_int2(const int2* p) {
    int2 v;
    asm volatile("ld.global.cs.v2.b32 {%0,%1}, [%2];" : "=r"(v.x), "=r"(v.y) : "l"(p));
    return v;
}
__device__ __forceinline__ void stcs_int2(int2* p, int2 v) {
    asm volatile("st.global.cs.v2.b32 [%0], {%1,%2};" :: "l"(p), "r"(v.x), "r"(v.y) : "memory");
}
__device__ __forceinline__ void stcs_float4(float4* p, float4 v) {
    asm volatile("st.global.cs.v4.f32 [%0], {%1,%2,%3,%4};"
                 :: "l"(p), "f"(v.x), "f"(v.y), "f"(v.z), "f"(v.w) : "memory");
}

// ------------------------- CSR build -------------------------
__global__ void zero_cnt_kernel() {
    int i = blockIdx.x * blockDim.x + threadIdx.x;
    if (i < N_NODES) g_cnt[i] = 0;
}

__global__ void hist_kernel(const int* __restrict__ erow) {
    int e = blockIdx.x * blockDim.x + threadIdx.x;
    if (e < N_EDGES) atomicAdd(&g_cnt[erow[e]], 1);
}

__global__ void scan1_kernel() {
    __shared__ int sh[256];
    int t = threadIdx.x;
    int base = blockIdx.x * SCAN_TILE + t * 4;
    int v[4];
#pragma unroll
    for (int j = 0; j < 4; j++)
        v[j] = (base + j < N_NODES) ? g_cnt[base + j] : 0;
    int s = v[0] + v[1] + v[2] + v[3];
    sh[t] = s;
    __syncthreads();
#pragma unroll
    for (int off = 1; off < 256; off <<= 1) {
        int x = (t >= off) ? sh[t - off] : 0;
        __syncthreads();
        sh[t] += x;
        __syncthreads();
    }
    int run = sh[t] - s;
#pragma unroll
    for (int j = 0; j < 4; j++) {
        if (base + j < N_NODES) g_start[base + j] = run;
        run += v[j];
    }
    if (t == 255) g_blocksums[blockIdx.x] = sh[255];
}

__global__ void scan2_kernel() {
    __shared__ int sh[256];
    int t = threadIdx.x;
    int v = (t < SCAN_BLOCKS) ? g_blocksums[t] : 0;
    sh[t] = v;
    __syncthreads();
#pragma unroll
    for (int off = 1; off < 256; off <<= 1) {
        int x = (t >= off) ? sh[t - off] : 0;
        __syncthreads();
        sh[t] += x;
        __syncthreads();
    }
    if (t < SCAN_BLOCKS) g_blocksums[t] = sh[t] - v;
}

__global__ void scan3_kernel() {
    int i = blockIdx.x * blockDim.x + threadIdx.x;
    if (i < N_NODES) {
        int s = g_start[i] + g_blocksums[i / SCAN_TILE];
        g_start[i] = s;
        g_cursor[i] = s;
    }
}

__global__ void fill_kernel(const int* __restrict__ erow,
                            const int* __restrict__ ecol,
                            const float* __restrict__ eval) {
    int e = blockIdx.x * blockDim.x + threadIdx.x;
    if (e < N_EDGES) {
        int r = erow[e];
        int pos = atomicAdd(&g_cursor[r], 1);
        stcs_int2(&g_edge_s[pos], make_int2(ecol[e], __float_as_int(eval[e])));
    }
}

// ------------------------- SpMM: warp per row, 4-wide unroll, streaming hints -------------------------
__global__ __launch_bounds__(256)
void spmm_csr_kernel(const float* __restrict__ ego) {
    int gw = (blockIdx.x * blockDim.x + threadIdx.x) >> 5;
    int lane = threadIdx.x & 31;
    if (gw >= N_NODES) return;
    int start = g_start[gw];
    int end = start + g_cnt[gw];
    const float4* ego4 = (const float4*)ego;
    float4 acc = make_float4(0.f, 0.f, 0.f, 0.f);
    int i = start;
    for (; i + 3 < end; i += 4) {
        int2 e0 = ldcs_int2(&g_edge_s[i]);
        int2 e1 = ldcs_int2(&g_edge_s[i + 1]);
        int2 e2 = ldcs_int2(&g_edge_s[i + 2]);
        int2 e3 = ldcs_int2(&g_edge_s[i + 3]);
        float4 m0 = ego4[(size_t)e0.x * 32 + lane];
        float4 m1 = ego4[(size_t)e1.x * 32 + lane];
        float4 m2 = ego4[(size_t)e2.x * 32 + lane];
        float4 m3 = ego4[(size_t)e3.x * 32 + lane];
        float v0 = __int_as_float(e0.y), v1 = __int_as_float(e1.y);
        float v2 = __int_as_float(e2.y), v3 = __int_as_float(e3.y);
        acc.x = fmaf(v0, m0.x, acc.x); acc.y = fmaf(v0, m0.y, acc.y);
        acc.z = fmaf(v0, m0.z, acc.z); acc.w = fmaf(v0, m0.w, acc.w);
        acc.x = fmaf(v1, m1.x, acc.x); acc.y = fmaf(v1, m1.y, acc.y);
        acc.z = fmaf(v1, m1.z, acc.z); acc.w = fmaf(v1, m1.w, acc.w);
        acc.x = fmaf(v2, m2.x, acc.x); acc.y = fmaf(v2, m2.y, acc.y);
        acc.z = fmaf(v2, m2.z, acc.z); acc.w = fmaf(v2, m2.w, acc.w);
        acc.x = fmaf(v3, m3.x, acc.x); acc.y = fmaf(v3, m3.y, acc.y);
        acc.z = fmaf(v3, m3.z, acc.z); acc.w = fmaf(v3, m3.w, acc.w);
    }
    for (; i < end; i++) {
        int2 e0 = ldcs_int2(&g_edge_s[i]);
        float v0 = __int_as_float(e0.y);
        float4 m0 = ego4[(size_t)e0.x * 32 + lane];
        acc.x = fmaf(v0, m0.x, acc.x); acc.y = fmaf(v0, m0.y, acc.y);
        acc.z = fmaf(v0, m0.z, acc.z); acc.w = fmaf(v0, m0.w, acc.w);
    }
    stcs_float4(&reinterpret_cast<float4*>(g_side)[(size_t)gw * 32 + lane], acc);
}

// ------------------------- W prep: transpose + split-bf16 -------------------------
__global__ void prep_w_kernel(const float* __restrict__ wgc, const float* __restrict__ wbi) {
    int i = blockIdx.x * blockDim.x + threadIdx.x;
    if (i >= 128 * 128) return;
    int k = i >> 7, n = i & 127;
    float vg = wgc[i];                     // wgc[k][n]
    float vb = wbi[i];
    __nv_bfloat16 gh = __float2bfloat16(vg);
    __nv_bfloat16 gl = __float2bfloat16(vg - __bfloat162float(gh));
    __nv_bfloat16 bh = __float2bfloat16(vb);
    __nv_bfloat16 bl = __float2bfloat16(vb - __bfloat162float(bh));
    int off = n * DSTRIDE + k;             // [n][k]
    g_W[off] = gh;
    g_W[128 * DSTRIDE + off] = gl;
    g_W[2 * 128 * DSTRIDE + off] = bh;
    g_W[3 * 128 * DSTRIDE + off] = bl;
}

// ------------------------- dense: persistent mma.sync bf16-split -------------------------
#define A_SHI 0
#define A_SLO (64 * DSTRIDE)
#define A_BHI (2 * 64 * DSTRIDE)
#define A_BLO (3 * 64 * DSTRIDE)
#define W_OFF (4 * 64 * DSTRIDE)
#define SMEM_BF16 (W_OFF + 4 * 128 * DSTRIDE)
#define FBIAS_BYTE (SMEM_BF16 * 2)
#define SQ_BYTE (FBIAS_BYTE + 1024)
#define DENSE_SMEM (SQ_BYTE + 512)         // ~210 KB

__device__ __forceinline__ void mma_bf16(float* c, const uint32_t* a, const uint32_t* b) {
    asm volatile("mma.sync.aligned.m16n8k16.row.col.f32.bf16.bf16.f32 "
                 "{%0,%1,%2,%3}, {%4,%5,%6,%7}, {%8,%9}, {%0,%1,%2,%3};"
                 : "+f"(c[0]), "+f"(c[1]), "+f"(c[2]), "+f"(c[3])
                 : "r"(a[0]), "r"(a[1]), "r"(a[2]), "r"(a[3]), "r"(b[0]), "r"(b[1]));
}

__device__ __forceinline__ uint32_t pack_bf16x2(float a, float b) {
    __nv_bfloat162 t;
    t.x = __float2bfloat16(a);
    t.y = __float2bfloat16(b);
    return *reinterpret_cast<uint32_t*>(&t);
}

__global__ __launch_bounds__(256, 1)
void dense_mma_kernel(const float* __restrict__ ego,
                      const float* __restrict__ bgc,
                      const float* __restrict__ bbi,
                      float* __restrict__ out) {
    extern __shared__ __nv_bfloat16 sm[];
    float* fbias = (float*)((char*)sm + FBIAS_BYTE);   // [0:128) bgc, [128:256) bbi
    float* sqbuf = (float*)((char*)sm + SQ_BYTE);      // [2][64]

    const int tid = threadIdx.x;
    const int w = tid >> 5, lane = tid & 31;
    const int mt = w >> 1;            // m-tile 0..3 (16 rows each)
    const int ch = w & 1;             // col half 0..1 (64 cols)
    const int g = lane >> 2, tig = lane & 3;
    const int arow = mt * 16 + g;

    // one-time: copy prepped W (139,264 B) + bias into smem
    {
        const float4* src = (const float4*)g_W;
        float4* dst = (float4*)(sm + W_OFF);
        for (int i = tid; i < (4 * 128 * DSTRIDE) / 8; i += 256) dst[i] = src[i];
    }
    if (tid < 128) fbias[tid] = bgc[tid];
    else fbias[tid] = bbi[tid - 128];

    const __nv_bfloat16* wGh = sm + W_OFF;
    const __nv_bfloat16* wGl = wGh + 128 * DSTRIDE;
    const __nv_bfloat16* wBh = wGl + 128 * DSTRIDE;
    const __nv_bfloat16* wBl = wBh + 128 * DSTRIDE;

    for (int tile = blockIdx.x; tile < N_TILES; tile += DENSE_GRID) {
        const long row0 = (long)tile * ROWS_PER_BLK;

        // stage A tiles: side hi/lo and (ego*side) hi/lo
        for (int i = tid; i < ROWS_PER_BLK * 32; i += 256) {
            int r = i >> 5, c4 = i & 31;
            long gr = row0 + r;
            float4 s4 = make_float4(0.f, 0.f, 0.f, 0.f);
            float4 b4 = s4;
            if (gr < N_NODES) {
                s4 = reinterpret_cast<const float4*>(g_side + gr * D)[c4];
                float4 e4 = reinterpret_cast<const float4*>(ego + gr * D)[c4];
                b4 = make_float4(s4.x * e4.x, s4.y * e4.y, s4.z * e4.z, s4.w * e4.w);
            }
            int off = r * DSTRIDE + c4 * 4;   // bf16 index, 8B aligned
            {
                uint32_t h0 = pack_bf16x2(s4.x, s4.y), h1 = pack_bf16x2(s4.z, s4.w);
                float r0 = s4.x - __bfloat162float(__float2bfloat16(s4.x));
                float r1 = s4.y - __bfloat162float(__float2bfloat16(s4.y));
                float r2 = s4.z - __bfloat162float(__float2bfloat16(s4.z));
                float r3 = s4.w - __bfloat162float(__float2bfloat16(s4.w));
                uint32_t l0 = pack_bf16x2(r0, r1), l1 = pack_bf16x2(r2, r3);
                *reinterpret_cast<uint2*>(sm + A_SHI + off) = make_uint2(h0, h1);
                *reinterpret_cast<uint2*>(sm + A_SLO + off) = make_uint2(l0, l1);
            }
            {
                uint32_t h0 = pack_bf16x2(b4.x, b4.y), h1 = pack_bf16x2(b4.z, b4.w);
                float r0 = b4.x - __bfloat162float(__float2bfloat16(b4.x));
                float r1 = b4.y - __bfloat162float(__float2bfloat16(b4.y));
                float r2 = b4.z - __bfloat162float(__float2bfloat16(b4.z));
                float r3 = b4.w - __bfloat162float(__float2bfloat16(b4.w));
                uint32_t l0 = pack_bf16x2(r0, r1), l1 = pack_bf16x2(r2, r3);
                *reinterpret_cast<uint2*>(sm + A_BHI + off) = make_uint2(h0, h1);
                *reinterpret_cast<uint2*>(sm + A_BLO + off) = make_uint2(l0, l1);
            }
        }
        __syncthreads();

        float accG[8][4];
        float accB[8][4];
#pragma unroll
        for (int nt = 0; nt < 8; nt++)
#pragma unroll
            for (int j = 0; j < 4; j++) { accG[nt][j] = 0.f; accB[nt][j] = 0.f; }

#pragma unroll 2
        for (int kc = 0; kc < 8; kc++) {
            const int k0 = kc * 16 + 2 * tig;
            uint32_t aSh[4], aSl[4], aBh[4], aBl[4];
            aSh[0] = *(const uint32_t*)(sm + A_SHI + arow * DSTRIDE + k0);
            aSh[1] = *(const uint32_t*)(sm + A_SHI + (arow + 8) * DSTRIDE + k0);
            aSh[2] = *(const uint32_t*)(sm + A_SHI + arow * DSTRIDE + k0 + 8);
            aSh[3] = *(const uint32_t*)(sm + A_SHI + (arow + 8) * DSTRIDE + k0 + 8);
            aSl[0] = *(const uint32_t*)(sm + A_SLO + arow * DSTRIDE + k0);
            aSl[1] = *(const uint32_t*)(sm + A_SLO + (arow + 8) * DSTRIDE + k0);
            aSl[2] = *(const uint32_t*)(sm + A_SLO + arow * DSTRIDE + k0 + 8);
            aSl[3] = *(const uint32_t*)(sm + A_SLO + (arow + 8) * DSTRIDE + k0 + 8);
            aBh[0] = *(const uint32_t*)(sm + A_BHI + arow * DSTRIDE + k0);
            aBh[1] = *(const uint32_t*)(sm + A_BHI + (arow + 8) * DSTRIDE + k0);
            aBh[2] = *(const uint32_t*)(sm + A_BHI + arow * DSTRIDE + k0 + 8);
            aBh[3] = *(const uint32_t*)(sm + A_BHI + (arow + 8) * DSTRIDE + k0 + 8);
            aBl[0] = *(const uint32_t*)(sm + A_BLO + arow * DSTRIDE + k0);
            aBl[1] = *(const uint32_t*)(sm + A_BLO + (arow + 8) * DSTRIDE + k0);
            aBl[2] = *(const uint32_t*)(sm + A_BLO + arow * DSTRIDE + k0 + 8);
            aBl[3] = *(const uint32_t*)(sm + A_BLO + (arow + 8) * DSTRIDE + k0 + 8);

#pragma unroll
            for (int nt = 0; nt < 8; nt++) {
                const int n = ch * 64 + nt * 8 + g;
                uint32_t bh[2], bl[2];
                bh[0] = *(const uint32_t*)(wGh + n * DSTRIDE + k0);
                bh[1] = *(const uint32_t*)(wGh + n * DSTRIDE + k0 + 8);
                bl[0] = *(const uint32_t*)(wGl + n * DSTRIDE + k0);
                bl[1] = *(const uint32_t*)(wGl + n * DSTRIDE + k0 + 8);
                mma_bf16(accG[nt], aSh, bh);
                mma_bf16(accG[nt], aSl, bh);
                mma_bf16(accG[nt], aSh, bl);
                bh[0] = *(const uint32_t*)(wBh + n * DSTRIDE + k0);
                bh[1] = *(const uint32_t*)(wBh + n * DSTRIDE + k0 + 8);
                bl[0] = *(const uint32_t*)(wBl + n * DSTRIDE + k0);
                bl[1] = *(const uint32_t*)(wBl + n * DSTRIDE + k0 + 8);
                mma_bf16(accB[nt], aBh, bh);
                mma_bf16(accB[nt], aBl, bh);
                mma_bf16(accB[nt], aBh, bl);
            }
        }

        // epilogue: bias + leaky + sum, then row L2-normalize
        float sq_lo = 0.f, sq_hi = 0.f;
#pragma unroll
        for (int nt = 0; nt < 8; nt++) {
            const int col = ch * 64 + nt * 8 + 2 * tig;
            float bg0 = fbias[col], bg1 = fbias[col + 1];
            float bb0 = fbias[128 + col], bb1 = fbias[128 + col + 1];
            float x, y;
            x = accG[nt][0] + bg0; x = fmaxf(x, 0.2f * x);
            y = accB[nt][0] + bb0; y = fmaxf(y, 0.2f * y);
            accG[nt][0] = x + y; sq_lo = fmaf(accG[nt][0], accG[nt][0], sq_lo);
            x = accG[nt][1] + bg1; x = fmaxf(x, 0.2f * x);
            y = accB[nt][1] + bb1; y = fmaxf(y, 0.2f * y);
            accG[nt][1] = x + y; sq_lo = fmaf(accG[nt][1], accG[nt][1], sq_lo);
            x = accG[nt][2] + bg0; x = fmaxf(x, 0.2f * x);
            y = accB[nt][2] + bb0; y = fmaxf(y, 0.2f * y);
            accG[nt][2] = x + y; sq_hi = fmaf(accG[nt][2], accG[nt][2], sq_hi);
            x = accG[nt][3] + bg1; x = fmaxf(x, 0.2f * x);
            y = accB[nt][3] + bb1; y = fmaxf(y, 0.2f * y);
            accG[nt][3] = x + y; sq_hi = fmaf(accG[nt][3], accG[nt][3], sq_hi);
        }
#pragma unroll
        for (int m = 1; m <= 2; m <<= 1) {
            sq_lo += __shfl_xor_sync(0xffffffffu, sq_lo, m);
            sq_hi += __shfl_xor_sync(0xffffffffu, sq_hi, m);
        }
        if (tig == 0) {
            sqbuf[ch * 64 + mt * 16 + g] = sq_lo;
            sqbuf[ch * 64 + mt * 16 + g + 8] = sq_hi;
        }
        __syncthreads();
        float tot_lo = sqbuf[mt * 16 + g] + sqbuf[64 + mt * 16 + g];
        float tot_hi = sqbuf[mt * 16 + g + 8] + sqbuf[64 + mt * 16 + g + 8];
        float rn_lo = rsqrtf(fmaxf(tot_lo, 1e-12f));
        float rn_hi = rsqrtf(fmaxf(tot_hi, 1e-12f));

        const long grow_lo = row0 + mt * 16 + g;
        const long grow_hi = grow_lo + 8;
#pragma unroll
        for (int nt = 0; nt < 8; nt++) {
            const int col = ch * 64 + nt * 8 + 2 * tig;
            if (grow_lo < N_NODES) {
                float2 o = make_float2(accG[nt][0] * rn_lo, accG[nt][1] * rn_lo);
                *reinterpret_cast<float2*>(out + grow_lo * D + col) = o;
            }
            if (grow_hi < N_NODES) {
                float2 o = make_float2(accG[nt][2] * rn_hi, accG[nt][3] * rn_hi);
                *reinterpret_cast<float2*>(out + grow_hi * D + col) = o;
            }
        }
        // next iteration's __syncthreads (after staging) fences A reuse; sqbuf
        // rewrite happens only after that sync, so no extra barrier needed here.
    }
}

// ------------------------- launch -------------------------
extern "C" void kernel_launch(void* const* d_in, const int* in_sizes, int n_in,
                              void* d_out, int out_size) {
    const int*   erow = (const int*)d_in[0];
    const int*   ecol = (const int*)d_in[1];
    const float* eval = (const float*)d_in[2];
    const float* ego  = (const float*)d_in[3];
    const float* wgc  = (const float*)d_in[4];
    const float* bgc  = (const float*)d_in[5];
    const float* wbi  = (const float*)d_in[6];
    const float* bbi  = (const float*)d_in[7];
    float* out = (float*)d_out;

    // CSR build
    zero_cnt_kernel<<<(N_NODES + 255) / 256, 256>>>();
    hist_kernel<<<(N_EDGES + 255) / 256, 256>>>(erow);
    scan1_kernel<<<SCAN_BLOCKS, 256>>>();
    scan2_kernel<<<1, 256>>>();
    scan3_kernel<<<(N_NODES + 255) / 256, 256>>>();
    fill_kernel<<<(N_EDGES + 255) / 256, 256>>>(erow, ecol, eval);

    // SpMM: warp per row
    long spmm_threads = (long)N_NODES * 32;
    spmm_csr_kernel<<<(int)((spmm_threads + 255) / 256), 256>>>(ego);

    // W prep + persistent dense tensor-core transform
    prep_w_kernel<<<64, 256>>>(wgc, wbi);
    cudaFuncSetAttribute(dense_mma_kernel, cudaFuncAttributeMaxDynamicSharedMemorySize, DENSE_SMEM);
    dense_mma_kernel<<<DENSE_GRID, 256, DENSE_SMEM>>>(ego, bgc, bbi, out);
}